// round 1
// baseline (speedup 1.0000x reference)
#include <cuda_runtime.h>
#include <math.h>

// Problem constants
#define BB 2
#define EE 1024
#define HH 16
#define DD 64
#define SS 4096            // 64*64 spatial tokens per batch
#define BNS (BB*SS)        // 8192 total tokens
#define E4 (4*EE)          // 4096 ffn hidden

// ---------------- device scratch (static: no allocation allowed) ----------------
__device__ float g_adad[(long)BB*EE*SS];   // 32MB  GRN1 output (channel-major), reused as o-proj out
__device__ float g_q  [(long)BNS*EE];      // 32MB  q (token-major)
__device__ float g_k  [(long)BNS*EE];      // 32MB
__device__ float g_v  [(long)BNS*EE];      // 32MB
__device__ float g_attn[(long)BNS*EE];     // 32MB  linear-attn output (token-major)
__device__ float g_work[(long)BNS*EE];     // 32MB  working (token-major)
__device__ float g_fn [(long)BNS*EE];      // 32MB  GRN2 output (token-major)
__device__ float g_h  [(long)BNS*E4];      // 128MB ffn hidden
__device__ float g_ffn[(long)BNS*EE];      // 32MB  ffn output
__device__ float g_kv  [BB*HH*DD*DD];      // 2MB-ish
__device__ float g_ksum[BB*HH*DD];
__device__ float g_sumsq[BB*EE];
__device__ float g_meangx[BB];

// ---------------- small helpers ----------------
__inline__ __device__ void blockReduce2(float& a, float& b) {
    #pragma unroll
    for (int off = 16; off > 0; off >>= 1) {
        a += __shfl_down_sync(0xffffffffu, a, off);
        b += __shfl_down_sync(0xffffffffu, b, off);
    }
    __shared__ float sa[8], sb[8];
    int w = threadIdx.x >> 5, l = threadIdx.x & 31;
    if (l == 0) { sa[w] = a; sb[w] = b; }
    __syncthreads();
    if (w == 0) {
        a = (l < 8) ? sa[l] : 0.f;
        b = (l < 8) ? sb[l] : 0.f;
        #pragma unroll
        for (int off = 4; off > 0; off >>= 1) {
            a += __shfl_down_sync(0xffu, a, off);
            b += __shfl_down_sync(0xffu, b, off);
        }
        if (l == 0) { sa[0] = a; sb[0] = b; }
    }
    __syncthreads();
    a = sa[0]; b = sb[0];
}

__global__ void zero_f(float* __restrict__ p, int n) {
    int i = blockIdx.x * blockDim.x + threadIdx.x;
    if (i < n) p[i] = 0.f;
}

// ---------------- GRN ----------------
// sum of squares over spatial dim, channel-major input [B][E][S]
__global__ __launch_bounds__(256) void grn_sumsq_cm(const float* __restrict__ x,
                                                    float* __restrict__ sumsq) {
    const float* xr = x + (long)blockIdx.x * SS;
    float acc = 0.f, dummy = 0.f;
    for (int i = threadIdx.x * 4; i < SS; i += 1024) {
        float4 v = *(const float4*)(xr + i);
        acc += v.x*v.x + v.y*v.y + v.z*v.z + v.w*v.w;
    }
    blockReduce2(acc, dummy);
    if (threadIdx.x == 0) sumsq[blockIdx.x] = acc;
}

// per-batch mean of gx = sqrt(sumsq) over channels
__global__ __launch_bounds__(256) void grn_mean(const float* __restrict__ sumsq,
                                                float* __restrict__ meangx) {
    int b = blockIdx.x;
    float s = 0.f, dummy = 0.f;
    for (int c = threadIdx.x; c < EE; c += 256) s += sqrtf(sumsq[b*EE + c]);
    blockReduce2(s, dummy);
    if (threadIdx.x == 0) meangx[b] = s / (float)EE;
}

// GRN apply, channel-major in/out: out = (1+g)*x*nx + beta + x
__global__ __launch_bounds__(256) void grn1_apply(const float* __restrict__ x,
                                                  const float* __restrict__ sumsq,
                                                  const float* __restrict__ meangx,
                                                  const float* __restrict__ gamma,
                                                  const float* __restrict__ beta,
                                                  float* __restrict__ out) {
    long i4 = ((long)blockIdx.x * 256 + threadIdx.x) * 4;
    int c = (int)((i4 >> 12) & 1023);
    int b = (int)(i4 >> 22);
    float nx = sqrtf(sumsq[b*EE + c]) / (meangx[b] + 1e-6f);
    float g1 = 1.f + gamma[c], be = beta[c];
    float4 v = *(const float4*)(x + i4);
    float4 o;
    o.x = g1*v.x*nx + be + v.x;
    o.y = g1*v.y*nx + be + v.y;
    o.z = g1*v.z*nx + be + v.z;
    o.w = g1*v.w*nx + be + v.w;
    *(float4*)(out + i4) = o;
}

// GRN2: sumsq over strided tokens (token-major working [B][S][C])
__global__ __launch_bounds__(256) void grn2_sumsq(const float* __restrict__ w,
                                                  float* __restrict__ sumsq) {
    int c = blockIdx.x * 256 + threadIdx.x;
    int b = blockIdx.z;
    long base = ((long)b * SS + (long)blockIdx.y * 256) * EE + c;
    float acc = 0.f;
    #pragma unroll 4
    for (int r = 0; r < 256; r++) {
        float v = w[base + (long)r * EE];
        acc += v * v;
    }
    atomicAdd(&sumsq[b*EE + c], acc);
}

// GRN apply, token-major in/out
__global__ __launch_bounds__(256) void grn2_apply(const float* __restrict__ x,
                                                  const float* __restrict__ sumsq,
                                                  const float* __restrict__ meangx,
                                                  const float* __restrict__ gamma,
                                                  const float* __restrict__ beta,
                                                  float* __restrict__ out) {
    long i4 = ((long)blockIdx.x * 256 + threadIdx.x) * 4;
    int c0 = (int)(i4 & 1023);
    int b = (int)(i4 >> 22);
    float4 g4 = *(const float4*)(gamma + c0);
    float4 b4 = *(const float4*)(beta + c0);
    float4 s4 = *(const float4*)(sumsq + b*EE + c0);
    float mg = meangx[b] + 1e-6f;
    float4 v = *(const float4*)(x + i4);
    float4 o;
    o.x = (1.f+g4.x) * v.x * (sqrtf(s4.x)/mg) + b4.x + v.x;
    o.y = (1.f+g4.y) * v.y * (sqrtf(s4.y)/mg) + b4.y + v.y;
    o.z = (1.f+g4.z) * v.z * (sqrtf(s4.z)/mg) + b4.z + v.z;
    o.w = (1.f+g4.w) * v.w * (sqrtf(s4.w)/mg) + b4.w + v.w;
    *(float4*)(out + i4) = o;
}

// ---------------- SGEMM: C[M,N] = A @ W^T + bias, W row-major [N,K] ----------------
// ALAY 0: A stored [K,M] (channel-major images).  ALAY 1: A row-major [M,K].
// EPI 0: bias.  EPI 1: bias + silu.
template<int ALAY, int EPI>
__global__ __launch_bounds__(256) void sgemm(const float* __restrict__ A,
                                             const float* __restrict__ W,
                                             const float* __restrict__ bias,
                                             float* __restrict__ C,
                                             int M, int N, int K,
                                             long aBatch, long cBatch) {
    __shared__ float As[8][128];
    __shared__ float Bs[8][128];
    A += (long)blockIdx.z * aBatch;
    C += (long)blockIdx.z * cBatch;
    const int m0 = blockIdx.y * 128, n0 = blockIdx.x * 128;
    const int tid = threadIdx.x;
    const int tx = tid & 15, ty = tid >> 4;

    float acc[8][8];
    #pragma unroll
    for (int i = 0; i < 8; i++)
        #pragma unroll
        for (int j = 0; j < 8; j++) acc[i][j] = 0.f;

    for (int k0 = 0; k0 < K; k0 += 8) {
        if (ALAY == 0) {
            int kk = tid >> 5, mm = (tid & 31) * 4;
            *(float4*)&As[kk][mm] = *(const float4*)(A + (long)(k0+kk)*M + m0 + mm);
        } else {
            int mm = tid >> 1, kk = (tid & 1) * 4;
            float4 a4 = *(const float4*)(A + (long)(m0+mm)*K + k0 + kk);
            As[kk+0][mm] = a4.x; As[kk+1][mm] = a4.y;
            As[kk+2][mm] = a4.z; As[kk+3][mm] = a4.w;
        }
        {
            int nn = tid >> 1, kk = (tid & 1) * 4;
            float4 b4 = *(const float4*)(W + (long)(n0+nn)*K + k0 + kk);
            Bs[kk+0][nn] = b4.x; Bs[kk+1][nn] = b4.y;
            Bs[kk+2][nn] = b4.z; Bs[kk+3][nn] = b4.w;
        }
        __syncthreads();
        #pragma unroll
        for (int kk = 0; kk < 8; kk++) {
            float a[8], b[8];
            #pragma unroll
            for (int i = 0; i < 8; i++) a[i] = As[kk][ty*8 + i];
            #pragma unroll
            for (int j = 0; j < 8; j++) b[j] = Bs[kk][tx*8 + j];
            #pragma unroll
            for (int i = 0; i < 8; i++)
                #pragma unroll
                for (int j = 0; j < 8; j++) acc[i][j] += a[i] * b[j];
        }
        __syncthreads();
    }
    #pragma unroll
    for (int i = 0; i < 8; i++) {
        long m = m0 + ty*8 + i;
        #pragma unroll
        for (int j = 0; j < 8; j += 4) {
            int n = n0 + tx*8 + j;
            float4 o;
            o.x = acc[i][j+0] + bias[n+0];
            o.y = acc[i][j+1] + bias[n+1];
            o.z = acc[i][j+2] + bias[n+2];
            o.w = acc[i][j+3] + bias[n+3];
            if (EPI == 1) {
                o.x = o.x / (1.f + expf(-o.x));
                o.y = o.y / (1.f + expf(-o.y));
                o.z = o.z / (1.f + expf(-o.z));
                o.w = o.w / (1.f + expf(-o.w));
            }
            *(float4*)(C + m*N + n) = o;
        }
    }
}

// ---------------- LayerNorm + (elu+1), in place, row = token (1024 features) ------
__global__ __launch_bounds__(256) void ln_elu(float* __restrict__ x,
                                              const float* __restrict__ w,
                                              const float* __restrict__ b) {
    float* xr = x + (long)blockIdx.x * EE;
    int tid = threadIdx.x;
    float4 v = *(const float4*)(xr + tid*4);
    float s  = v.x + v.y + v.z + v.w;
    float sq = v.x*v.x + v.y*v.y + v.z*v.z + v.w*v.w;
    blockReduce2(s, sq);
    float mean = s / (float)EE;
    float var = sq / (float)EE - mean*mean;
    float rstd = rsqrtf(var + 1e-5f);
    float4 wv = *(const float4*)(w + tid*4);
    float4 bv = *(const float4*)(b + tid*4);
    float y;
    y = (v.x-mean)*rstd*wv.x + bv.x; v.x = (y > 0.f) ? y + 1.f : expf(y);
    y = (v.y-mean)*rstd*wv.y + bv.y; v.y = (y > 0.f) ? y + 1.f : expf(y);
    y = (v.z-mean)*rstd*wv.z + bv.z; v.z = (y > 0.f) ? y + 1.f : expf(y);
    y = (v.w-mean)*rstd*wv.w + bv.w; v.w = (y > 0.f) ? y + 1.f : expf(y);
    *(float4*)(xr + tid*4) = v;
}

// ---------------- linear attention: kv_sum + k_sum (split-K over tokens) ----------
__global__ __launch_bounds__(256) void kvsum_kernel(const float* __restrict__ k,
                                                    const float* __restrict__ v,
                                                    float* __restrict__ kv,
                                                    float* __restrict__ ksum) {
    int bh = blockIdx.x;               // 0..31
    int b = bh >> 4, h = bh & 15;
    int tid = threadIdx.x;
    __shared__ float ks[16][68], vs[16][68];
    int d0 = (tid >> 4) * 4, e0 = (tid & 15) * 4;
    float acc[4][4] = {};
    float accks[4] = {};
    long base = ((long)b * SS + (long)blockIdx.y * 256) * EE + h * DD;
    int ltok = tid >> 4, lc = (tid & 15) * 4;
    for (int t0 = 0; t0 < 256; t0 += 16) {
        *(float4*)&ks[ltok][lc] = *(const float4*)(k + base + (long)(t0+ltok)*EE + lc);
        *(float4*)&vs[ltok][lc] = *(const float4*)(v + base + (long)(t0+ltok)*EE + lc);
        __syncthreads();
        #pragma unroll
        for (int t = 0; t < 16; t++) {
            float a[4], bb[4];
            #pragma unroll
            for (int i = 0; i < 4; i++) a[i] = ks[t][d0+i];
            #pragma unroll
            for (int j = 0; j < 4; j++) bb[j] = vs[t][e0+j];
            #pragma unroll
            for (int i = 0; i < 4; i++)
                #pragma unroll
                for (int j = 0; j < 4; j++) acc[i][j] += a[i]*bb[j];
            if (e0 == 0) {
                #pragma unroll
                for (int i = 0; i < 4; i++) accks[i] += a[i];
            }
        }
        __syncthreads();
    }
    long kvbase = (long)bh * DD * DD;
    #pragma unroll
    for (int i = 0; i < 4; i++)
        #pragma unroll
        for (int j = 0; j < 4; j++)
            atomicAdd(&kv[kvbase + (d0+i)*DD + e0+j], acc[i][j]);
    if (e0 == 0)
        #pragma unroll
        for (int i = 0; i < 4; i++) atomicAdd(&ksum[bh*DD + d0+i], accks[i]);
}

// attn = (q @ kv) / (q . ksum + 1e-8), 64 tokens per block
__global__ __launch_bounds__(256) void attn_apply_kernel(const float* __restrict__ q,
                                                         const float* __restrict__ kv,
                                                         const float* __restrict__ ksum,
                                                         float* __restrict__ attn) {
    int bh = blockIdx.x, sblk = blockIdx.y;
    int b = bh >> 4, h = bh & 15;
    int tid = threadIdx.x;
    __shared__ float qs[64][68];
    __shared__ float kvs[64][64];
    __shared__ float kss[64];
    long kvbase = (long)bh * DD * DD;
    #pragma unroll
    for (int r = 0; r < 4; r++) {
        int idx = (r*256 + tid) * 4;
        *(float4*)&kvs[idx >> 6][idx & 63] = *(const float4*)(kv + kvbase + idx);
    }
    if (tid < 64) kss[tid] = ksum[bh*DD + tid];
    long qbase = ((long)b * SS + (long)sblk * 64) * EE + h * DD;
    int ltok = tid >> 4, lc = (tid & 15) * 4;
    #pragma unroll
    for (int r = 0; r < 4; r++)
        *(float4*)&qs[ltok + r*16][lc] =
            *(const float4*)(q + qbase + (long)(ltok + r*16)*EE + lc);
    __syncthreads();
    int tok = tid >> 2, e0 = (tid & 3) * 16;
    float num[16] = {};
    float den = 0.f;
    #pragma unroll 8
    for (int d = 0; d < 64; d++) {
        float qd = qs[tok][d];
        den += qd * kss[d];
        #pragma unroll
        for (int j = 0; j < 16; j++) num[j] += qd * kvs[d][e0+j];
    }
    float r = 1.f / (den + 1e-8f);
    long obase = ((long)b * SS + (long)sblk * 64 + tok) * EE + h * DD + e0;
    #pragma unroll
    for (int j = 0; j < 16; j += 4) {
        float4 o = make_float4(num[j]*r, num[j+1]*r, num[j+2]*r, num[j+3]*r);
        *(float4*)(attn + obase + j) = o;
    }
}

// ---------------- residual / transpose kernels ----------------
// working[b,s,c] = qimg[b,c,s] + attn_out[b,s,c] * attn_scalar[c]
__global__ void make_working(const float* __restrict__ qimg,
                             const float* __restrict__ attn_out,
                             const float* __restrict__ ascal,
                             float* __restrict__ work) {
    __shared__ float t[32][33];
    int sx = blockIdx.x * 32, cy = blockIdx.y * 32, b = blockIdx.z;
    int x = threadIdx.x;
    for (int r = threadIdx.y; r < 32; r += 8)
        t[r][x] = qimg[((long)b*EE + cy + r)*SS + sx + x];
    __syncthreads();
    for (int r = threadIdx.y; r < 32; r += 8) {
        long o = ((long)b*SS + sx + r)*EE + cy + x;
        work[o] = t[x][r] + attn_out[o] * ascal[cy + x];
    }
}

// out[b,c,s] = qimg[b,c,s] + (work[b,s,c] + ffn[b,s,c]*ffn_scalar[c]) * final_scalar[c]
__global__ void final_kernel(const float* __restrict__ qimg,
                             const float* __restrict__ work,
                             const float* __restrict__ ffn,
                             const float* __restrict__ fscal,
                             const float* __restrict__ finscal,
                             float* __restrict__ out) {
    __shared__ float t[32][33];
    int sx = blockIdx.x * 32, cy = blockIdx.y * 32, b = blockIdx.z;
    int x = threadIdx.x;
    for (int r = threadIdx.y; r < 32; r += 8) {
        long o = ((long)b*SS + sx + r)*EE + cy + x;
        t[r][x] = (work[o] + ffn[o] * fscal[cy + x]) * finscal[cy + x];
    }
    __syncthreads();
    for (int r = threadIdx.y; r < 32; r += 8) {
        long o = ((long)b*EE + cy + r)*SS + sx + x;
        out[o] = qimg[o] + t[x][r];
    }
}

// ---------------- host launcher ----------------
extern "C" void kernel_launch(void* const* d_in, const int* in_sizes, int n_in,
                              void* d_out, int out_size) {
    const float* qimg   = (const float*)d_in[0];
    const float* kimg   = (const float*)d_in[1];
    const float* vimg   = (const float*)d_in[2];
    const float* grn1_g = (const float*)d_in[3];
    const float* grn1_b = (const float*)d_in[4];
    const float* q_w    = (const float*)d_in[5];
    const float* q_b    = (const float*)d_in[6];
    const float* k_w    = (const float*)d_in[7];
    const float* k_b    = (const float*)d_in[8];
    const float* v_w    = (const float*)d_in[9];
    const float* v_b    = (const float*)d_in[10];
    const float* o_w    = (const float*)d_in[11];
    const float* o_b    = (const float*)d_in[12];
    const float* lnq_w  = (const float*)d_in[13];
    const float* lnq_b  = (const float*)d_in[14];
    const float* lnk_w  = (const float*)d_in[15];
    const float* lnk_b  = (const float*)d_in[16];
    const float* ascal  = (const float*)d_in[17];
    const float* grn2_g = (const float*)d_in[18];
    const float* grn2_b = (const float*)d_in[19];
    const float* w1     = (const float*)d_in[20];
    const float* b1     = (const float*)d_in[21];
    const float* w2     = (const float*)d_in[22];
    const float* b2     = (const float*)d_in[23];
    const float* fscal  = (const float*)d_in[24];
    const float* finscal= (const float*)d_in[25];

    float *adad, *qb, *kb, *vb, *attn, *work, *fn, *hbuf, *ffn, *kv, *ksum, *sumsq, *meang;
    cudaGetSymbolAddress((void**)&adad, g_adad);
    cudaGetSymbolAddress((void**)&qb,   g_q);
    cudaGetSymbolAddress((void**)&kb,   g_k);
    cudaGetSymbolAddress((void**)&vb,   g_v);
    cudaGetSymbolAddress((void**)&attn, g_attn);
    cudaGetSymbolAddress((void**)&work, g_work);
    cudaGetSymbolAddress((void**)&fn,   g_fn);
    cudaGetSymbolAddress((void**)&hbuf, g_h);
    cudaGetSymbolAddress((void**)&ffn,  g_ffn);
    cudaGetSymbolAddress((void**)&kv,   g_kv);
    cudaGetSymbolAddress((void**)&ksum, g_ksum);
    cudaGetSymbolAddress((void**)&sumsq,g_sumsq);
    cudaGetSymbolAddress((void**)&meang,g_meangx);

    const long ES = (long)EE * SS;   // per-batch batch stride (both layouts)

    // GRN1 on query image
    grn_sumsq_cm<<<BB*EE, 256>>>(qimg, sumsq);
    grn_mean<<<BB, 256>>>(sumsq, meang);
    grn1_apply<<<(int)(BB*ES/1024), 256>>>(qimg, sumsq, meang, grn1_g, grn1_b, adad);

    // Q/K/V projections (channel-major A) -> token-major outputs
    sgemm<0,0><<<dim3(EE/128, SS/128, BB), 256>>>(adad, q_w, q_b, qb, SS, EE, EE, ES, ES);
    sgemm<0,0><<<dim3(EE/128, SS/128, BB), 256>>>(kimg, k_w, k_b, kb, SS, EE, EE, ES, ES);
    sgemm<0,0><<<dim3(EE/128, SS/128, BB), 256>>>(vimg, v_w, v_b, vb, SS, EE, EE, ES, ES);

    // LayerNorm + elu+1 (in place)
    ln_elu<<<BNS, 256>>>(qb, lnq_w, lnq_b);
    ln_elu<<<BNS, 256>>>(kb, lnk_w, lnk_b);

    // linear attention
    zero_f<<<(BB*HH*DD*DD + 255)/256, 256>>>(kv, BB*HH*DD*DD);
    zero_f<<<(BB*HH*DD + 255)/256, 256>>>(ksum, BB*HH*DD);
    kvsum_kernel<<<dim3(BB*HH, 16), 256>>>(kb, vb, kv, ksum);
    attn_apply_kernel<<<dim3(BB*HH, SS/64), 256>>>(qb, kv, ksum, attn);

    // O projection (token-major, batches merged), output into adad (reused)
    sgemm<1,0><<<dim3(EE/128, BNS/128, 1), 256>>>(attn, o_w, o_b, adad, BNS, EE, EE, 0, 0);

    // working = qimg^T + oproj * attn_scalar (token-major)
    make_working<<<dim3(SS/32, EE/32, BB), dim3(32,8)>>>(qimg, adad, ascal, work);

    // GRN2 on working (token-major)
    zero_f<<<(BB*EE + 255)/256, 256>>>(sumsq, BB*EE);
    grn2_sumsq<<<dim3(EE/256, SS/256, BB), 256>>>(work, sumsq);
    grn_mean<<<BB, 256>>>(sumsq, meang);
    grn2_apply<<<(int)(BB*ES/1024), 256>>>(work, sumsq, meang, grn2_g, grn2_b, fn);

    // FFN
    sgemm<1,1><<<dim3(E4/128, BNS/128, 1), 256>>>(fn, w1, b1, hbuf, BNS, E4, EE, 0, 0);
    sgemm<1,0><<<dim3(EE/128, BNS/128, 1), 256>>>(hbuf, w2, b2, ffn, BNS, EE, E4, 0, 0);

    // final residual (transpose back to channel-major)
    final_kernel<<<dim3(SS/32, EE/32, BB), dim3(32,8)>>>(qimg, work, ffn, fscal, finscal,
                                                         (float*)d_out);
}

// round 3
// speedup vs baseline: 2.4427x; 2.4427x over previous
#include <cuda_runtime.h>
#include <cuda_bf16.h>
#include <math.h>
#include <stdint.h>

// Problem constants
#define BB 2
#define EE 1024
#define HH 16
#define DD 64
#define SS 4096            // 64*64 spatial tokens per batch
#define BNS (BB*SS)        // 8192 total tokens
#define E4 (4*EE)          // 4096 ffn hidden

typedef __nv_bfloat16 bf16;
typedef __nv_bfloat162 bf162;

// ---------------- device scratch ----------------
__device__ float g_adad[(long)BNS*EE];
__device__ float g_q   [(long)BNS*EE];
__device__ float g_k   [(long)BNS*EE];
__device__ float g_v   [(long)BNS*EE];
__device__ float g_attn[(long)BNS*EE];
__device__ float g_work[(long)BNS*EE];
__device__ float g_fn  [(long)BNS*EE];
__device__ bf16  g_xh  [(long)BNS*EE];
__device__ bf16  g_xl  [(long)BNS*EE];
__device__ bf16  g_wh  [(long)E4*EE];
__device__ bf16  g_wl  [(long)E4*EE];
__device__ bf16  g_hh  [(long)BNS*E4];
__device__ bf16  g_hl  [(long)BNS*E4];
__device__ float g_kv  [BB*HH*DD*DD];
__device__ float g_ksum[BB*HH*DD];
__device__ float g_sumsq[BB*EE];
__device__ float g_meangx[BB];

// ================= helpers =================
__device__ __forceinline__ uint32_t smem_u32(const void* p) {
    uint32_t a;
    asm("{ .reg .u64 t; cvta.to.shared.u64 t, %1; cvt.u32.u64 %0, t; }" : "=r"(a) : "l"(p));
    return a;
}
__device__ __forceinline__ void cp16(uint32_t dst, const void* src) {
    asm volatile("cp.async.cg.shared.global [%0], [%1], 16;" :: "r"(dst), "l"(src));
}
__device__ __forceinline__ uint32_t lds32(uint32_t a) {
    uint32_t v;
    asm volatile("ld.shared.u32 %0, [%1];" : "=r"(v) : "r"(a));
    return v;
}
__device__ __forceinline__ void mma16816(float* c, const uint32_t* a, const uint32_t* b) {
    asm volatile(
        "mma.sync.aligned.m16n8k16.row.col.f32.bf16.bf16.f32 "
        "{%0,%1,%2,%3}, {%4,%5,%6,%7}, {%8,%9}, {%0,%1,%2,%3};"
        : "+f"(c[0]), "+f"(c[1]), "+f"(c[2]), "+f"(c[3])
        : "r"(a[0]), "r"(a[1]), "r"(a[2]), "r"(a[3]), "r"(b[0]), "r"(b[1]));
}

// ================= GEMM: C[M,N] = (Ah+Al)(Wh+Wl)^T + bias (3-pass bf16) =====
// A row-major [M,K] hi/lo, W row-major [N,K] hi/lo.
// Block 128x128, KT=32, 8 warps (2 M x 4 N), warp tile 64x32.
// smem tile layout: [128 rows][pitch 80B] per matrix; 4 matrices/stage, 2 stages.
#define TPITCH 80
#define TBYTES (128*TPITCH)          // 10240
#define STAGEB (4*TBYTES)            // 40960
#define GSMEM  (2*STAGEB)            // 81920

template<int EPI>
__global__ __launch_bounds__(256, 2) void gemm_hmma(
    const bf16* __restrict__ Ah, const bf16* __restrict__ Al,
    const bf16* __restrict__ Wh, const bf16* __restrict__ Wl,
    const float* __restrict__ bias,
    float* __restrict__ C, bf16* __restrict__ CH, bf16* __restrict__ CL,
    int M, int N, int K)
{
    extern __shared__ char sm[];
    const uint32_t sbase = smem_u32(sm);
    const int tid = threadIdx.x;
    const int lane = tid & 31, wid = tid >> 5;
    const int warp_m = wid >> 2, warp_n = wid & 3;
    const int m0 = blockIdx.y * 128, n0 = blockIdx.x * 128;
    const int lrow = lane >> 2, lpair = lane & 3;

    float acc[4][4][4];
    #pragma unroll
    for (int i = 0; i < 4; i++)
        #pragma unroll
        for (int j = 0; j < 4; j++)
            #pragma unroll
            for (int t = 0; t < 4; t++) acc[i][j][t] = 0.f;

    const int nk = K >> 5;

    // ---- stage loader: 512 (row,chunk) pairs for A, 512 for B ----
    auto load_stage = [&](int buf, int kc) {
        const long kq = (long)kc * 32;
        uint32_t sb = sbase + buf * STAGEB;
        #pragma unroll
        for (int i = 0; i < 2; i++) {
            int p = tid + i * 256;
            int row = p >> 2, ch = p & 3;
            long goff = (long)(m0 + row) * K + kq + ch * 8;
            uint32_t d = sb + row * TPITCH + ch * 16;
            cp16(d,            Ah + goff);
            cp16(d + TBYTES,   Al + goff);
            long boff = (long)(n0 + row) * K + kq + ch * 8;
            cp16(d + 2*TBYTES, Wh + boff);
            cp16(d + 3*TBYTES, Wl + boff);
        }
        asm volatile("cp.async.commit_group;");
    };

    load_stage(0, 0);
    if (nk > 1) load_stage(1, 1);

    for (int kc = 0; kc < nk; kc++) {
        const int buf = kc & 1;
        if (kc + 2 < nk) asm volatile("cp.async.wait_group 1;");
        else             asm volatile("cp.async.wait_group 0;");
        __syncthreads();

        const uint32_t aHb = sbase + buf * STAGEB;
        const uint32_t aLb = aHb + TBYTES;
        const uint32_t bHb = aHb + 2*TBYTES;
        const uint32_t bLb = aHb + 3*TBYTES;

        #pragma unroll
        for (int s = 0; s < 2; s++) {
            const uint32_t koff = (s * 8 + lpair) * 4;
            uint32_t aH[4][4], bH[4][2];
            #pragma unroll
            for (int mt = 0; mt < 4; mt++) {
                uint32_t r = (warp_m * 64 + mt * 16 + lrow) * TPITCH;
                aH[mt][0] = lds32(aHb + r + koff);
                aH[mt][1] = lds32(aHb + r + 8*TPITCH + koff);
                aH[mt][2] = lds32(aHb + r + koff + 16);
                aH[mt][3] = lds32(aHb + r + 8*TPITCH + koff + 16);
            }
            #pragma unroll
            for (int nt = 0; nt < 4; nt++) {
                uint32_t r = (warp_n * 32 + nt * 8 + lrow) * TPITCH;
                bH[nt][0] = lds32(bHb + r + koff);
                bH[nt][1] = lds32(bHb + r + koff + 16);
            }
            #pragma unroll
            for (int mt = 0; mt < 4; mt++)
                #pragma unroll
                for (int nt = 0; nt < 4; nt++)
                    mma16816(acc[mt][nt], aH[mt], bH[nt]);
            // pass 2: Al x Bh
            {
                uint32_t aL[4][4];
                #pragma unroll
                for (int mt = 0; mt < 4; mt++) {
                    uint32_t r = (warp_m * 64 + mt * 16 + lrow) * TPITCH;
                    aL[mt][0] = lds32(aLb + r + koff);
                    aL[mt][1] = lds32(aLb + r + 8*TPITCH + koff);
                    aL[mt][2] = lds32(aLb + r + koff + 16);
                    aL[mt][3] = lds32(aLb + r + 8*TPITCH + koff + 16);
                }
                #pragma unroll
                for (int mt = 0; mt < 4; mt++)
                    #pragma unroll
                    for (int nt = 0; nt < 4; nt++)
                        mma16816(acc[mt][nt], aL[mt], bH[nt]);
            }
            // pass 3: Ah x Bl
            {
                uint32_t bL[4][2];
                #pragma unroll
                for (int nt = 0; nt < 4; nt++) {
                    uint32_t r = (warp_n * 32 + nt * 8 + lrow) * TPITCH;
                    bL[nt][0] = lds32(bLb + r + koff);
                    bL[nt][1] = lds32(bLb + r + koff + 16);
                }
                #pragma unroll
                for (int mt = 0; mt < 4; mt++)
                    #pragma unroll
                    for (int nt = 0; nt < 4; nt++)
                        mma16816(acc[mt][nt], aH[mt], bL[nt]);
            }
        }
        __syncthreads();
        if (kc + 2 < nk) load_stage(buf, kc + 2);
    }

    // ---- epilogue ----
    #pragma unroll
    for (int mt = 0; mt < 4; mt++) {
        #pragma unroll
        for (int nt = 0; nt < 4; nt++) {
            long row = m0 + warp_m * 64 + mt * 16 + lrow;
            int col = n0 + warp_n * 32 + nt * 8 + lpair * 2;
            float b0 = bias[col], b1 = bias[col + 1];
            #pragma unroll
            for (int half = 0; half < 2; half++) {
                long r = row + half * 8;
                float v0 = acc[mt][nt][half*2 + 0] + b0;
                float v1 = acc[mt][nt][half*2 + 1] + b1;
                if (EPI == 0) {
                    *(float2*)(C + r * N + col) = make_float2(v0, v1);
                } else {
                    v0 = v0 / (1.f + expf(-v0));
                    v1 = v1 / (1.f + expf(-v1));
                    bf16 h0 = __float2bfloat16(v0);
                    bf16 h1 = __float2bfloat16(v1);
                    bf16 l0 = __float2bfloat16(v0 - __bfloat162float(h0));
                    bf16 l1 = __float2bfloat16(v1 - __bfloat162float(h1));
                    *(bf162*)(CH + r * N + col) = __halves2bfloat162(h0, h1);
                    *(bf162*)(CL + r * N + col) = __halves2bfloat162(l0, l1);
                }
            }
        }
    }
}

// ================= fp32 -> bf16 hi/lo converters =================
__global__ __launch_bounds__(256) void cvt_split(const float* __restrict__ x,
                                                 bf16* __restrict__ oh,
                                                 bf16* __restrict__ ol) {
    long i = ((long)blockIdx.x * 256 + threadIdx.x) * 4;
    float4 v = *(const float4*)(x + i);
    bf16 h0 = __float2bfloat16(v.x), h1 = __float2bfloat16(v.y);
    bf16 h2 = __float2bfloat16(v.z), h3 = __float2bfloat16(v.w);
    bf16 l0 = __float2bfloat16(v.x - __bfloat162float(h0));
    bf16 l1 = __float2bfloat16(v.y - __bfloat162float(h1));
    bf16 l2 = __float2bfloat16(v.z - __bfloat162float(h2));
    bf16 l3 = __float2bfloat16(v.w - __bfloat162float(h3));
    *(bf162*)(oh + i)     = __halves2bfloat162(h0, h1);
    *(bf162*)(oh + i + 2) = __halves2bfloat162(h2, h3);
    *(bf162*)(ol + i)     = __halves2bfloat162(l0, l1);
    *(bf162*)(ol + i + 2) = __halves2bfloat162(l2, l3);
}

// transpose [B,E,S] fp32 -> [B,S,E] bf16 hi/lo
__global__ void cvt_T(const float* __restrict__ x, bf16* __restrict__ oh,
                      bf16* __restrict__ ol) {
    __shared__ float t[32][33];
    int sx = blockIdx.x * 32, cy = blockIdx.y * 32, b = blockIdx.z;
    int lx = threadIdx.x;
    for (int r = threadIdx.y; r < 32; r += 8)
        t[r][lx] = x[((long)b * EE + cy + r) * SS + sx + lx];
    __syncthreads();
    for (int r = threadIdx.y; r < 32; r += 8) {
        float v = t[lx][r];
        long o = ((long)b * SS + sx + r) * EE + cy + lx;
        bf16 h = __float2bfloat16(v);
        oh[o] = h;
        ol[o] = __float2bfloat16(v - __bfloat162float(h));
    }
}

// ---------------- small helpers ----------------
__inline__ __device__ void blockReduce2(float& a, float& b) {
    #pragma unroll
    for (int off = 16; off > 0; off >>= 1) {
        a += __shfl_down_sync(0xffffffffu, a, off);
        b += __shfl_down_sync(0xffffffffu, b, off);
    }
    __shared__ float sa[8], sb[8];
    int w = threadIdx.x >> 5, l = threadIdx.x & 31;
    if (l == 0) { sa[w] = a; sb[w] = b; }
    __syncthreads();
    if (w == 0) {
        a = (l < 8) ? sa[l] : 0.f;
        b = (l < 8) ? sb[l] : 0.f;
        #pragma unroll
        for (int off = 4; off > 0; off >>= 1) {
            a += __shfl_down_sync(0xffu, a, off);
            b += __shfl_down_sync(0xffu, b, off);
        }
        if (l == 0) { sa[0] = a; sb[0] = b; }
    }
    __syncthreads();
    a = sa[0]; b = sb[0];
}

__global__ void zero_f(float* __restrict__ p, int n) {
    int i = blockIdx.x * blockDim.x + threadIdx.x;
    if (i < n) p[i] = 0.f;
}

// ---------------- GRN ----------------
__global__ __launch_bounds__(256) void grn_sumsq_cm(const float* __restrict__ x,
                                                    float* __restrict__ sumsq) {
    const float* xr = x + (long)blockIdx.x * SS;
    float acc = 0.f, dummy = 0.f;
    for (int i = threadIdx.x * 4; i < SS; i += 1024) {
        float4 v = *(const float4*)(xr + i);
        acc += v.x*v.x + v.y*v.y + v.z*v.z + v.w*v.w;
    }
    blockReduce2(acc, dummy);
    if (threadIdx.x == 0) sumsq[blockIdx.x] = acc;
}

__global__ __launch_bounds__(256) void grn_mean(const float* __restrict__ sumsq,
                                                float* __restrict__ meangx) {
    int b = blockIdx.x;
    float s = 0.f, dummy = 0.f;
    for (int c = threadIdx.x; c < EE; c += 256) s += sqrtf(sumsq[b*EE + c]);
    blockReduce2(s, dummy);
    if (threadIdx.x == 0) meangx[b] = s / (float)EE;
}

__global__ __launch_bounds__(256) void grn1_apply(const float* __restrict__ x,
                                                  const float* __restrict__ sumsq,
                                                  const float* __restrict__ meangx,
                                                  const float* __restrict__ gamma,
                                                  const float* __restrict__ beta,
                                                  float* __restrict__ out) {
    long i4 = ((long)blockIdx.x * 256 + threadIdx.x) * 4;
    int c = (int)((i4 >> 12) & 1023);
    int b = (int)(i4 >> 22);
    float nx = sqrtf(sumsq[b*EE + c]) / (meangx[b] + 1e-6f);
    float g1 = 1.f + gamma[c], be = beta[c];
    float4 v = *(const float4*)(x + i4);
    float4 o;
    o.x = g1*v.x*nx + be + v.x;
    o.y = g1*v.y*nx + be + v.y;
    o.z = g1*v.z*nx + be + v.z;
    o.w = g1*v.w*nx + be + v.w;
    *(float4*)(out + i4) = o;
}

__global__ __launch_bounds__(256) void grn2_sumsq(const float* __restrict__ w,
                                                  float* __restrict__ sumsq) {
    int c = blockIdx.x * 256 + threadIdx.x;
    int b = blockIdx.z;
    long base = ((long)b * SS + (long)blockIdx.y * 256) * EE + c;
    float acc = 0.f;
    #pragma unroll 4
    for (int r = 0; r < 256; r++) {
        float v = w[base + (long)r * EE];
        acc += v * v;
    }
    atomicAdd(&sumsq[b*EE + c], acc);
}

__global__ __launch_bounds__(256) void grn2_apply(const float* __restrict__ x,
                                                  const float* __restrict__ sumsq,
                                                  const float* __restrict__ meangx,
                                                  const float* __restrict__ gamma,
                                                  const float* __restrict__ beta,
                                                  float* __restrict__ out) {
    long i4 = ((long)blockIdx.x * 256 + threadIdx.x) * 4;
    int c0 = (int)(i4 & 1023);
    int b = (int)(i4 >> 22);
    float4 g4 = *(const float4*)(gamma + c0);
    float4 b4 = *(const float4*)(beta + c0);
    float4 s4 = *(const float4*)(sumsq + b*EE + c0);
    float mg = meangx[b] + 1e-6f;
    float4 v = *(const float4*)(x + i4);
    float4 o;
    o.x = (1.f+g4.x) * v.x * (sqrtf(s4.x)/mg) + b4.x + v.x;
    o.y = (1.f+g4.y) * v.y * (sqrtf(s4.y)/mg) + b4.y + v.y;
    o.z = (1.f+g4.z) * v.z * (sqrtf(s4.z)/mg) + b4.z + v.z;
    o.w = (1.f+g4.w) * v.w * (sqrtf(s4.w)/mg) + b4.w + v.w;
    *(float4*)(out + i4) = o;
}

// ---------------- LayerNorm + (elu+1) ----------------
__global__ __launch_bounds__(256) void ln_elu(float* __restrict__ x,
                                              const float* __restrict__ w,
                                              const float* __restrict__ b) {
    float* xr = x + (long)blockIdx.x * EE;
    int tid = threadIdx.x;
    float4 v = *(const float4*)(xr + tid*4);
    float s  = v.x + v.y + v.z + v.w;
    float sq = v.x*v.x + v.y*v.y + v.z*v.z + v.w*v.w;
    blockReduce2(s, sq);
    float mean = s / (float)EE;
    float var = sq / (float)EE - mean*mean;
    float rstd = rsqrtf(var + 1e-5f);
    float4 wv = *(const float4*)(w + tid*4);
    float4 bv = *(const float4*)(b + tid*4);
    float y;
    y = (v.x-mean)*rstd*wv.x + bv.x; v.x = (y > 0.f) ? y + 1.f : expf(y);
    y = (v.y-mean)*rstd*wv.y + bv.y; v.y = (y > 0.f) ? y + 1.f : expf(y);
    y = (v.z-mean)*rstd*wv.z + bv.z; v.z = (y > 0.f) ? y + 1.f : expf(y);
    y = (v.w-mean)*rstd*wv.w + bv.w; v.w = (y > 0.f) ? y + 1.f : expf(y);
    *(float4*)(xr + tid*4) = v;
}

// ---------------- linear attention ----------------
__global__ __launch_bounds__(256) void kvsum_kernel(const float* __restrict__ k,
                                                    const float* __restrict__ v,
                                                    float* __restrict__ kv,
                                                    float* __restrict__ ksum) {
    int bh = blockIdx.x;
    int b = bh >> 4, h = bh & 15;
    int tid = threadIdx.x;
    __shared__ float ks[16][68], vs[16][68];
    int d0 = (tid >> 4) * 4, e0 = (tid & 15) * 4;
    float acc[4][4] = {};
    float accks[4] = {};
    long base = ((long)b * SS + (long)blockIdx.y * 256) * EE + h * DD;
    int ltok = tid >> 4, lc = (tid & 15) * 4;
    for (int t0 = 0; t0 < 256; t0 += 16) {
        *(float4*)&ks[ltok][lc] = *(const float4*)(k + base + (long)(t0+ltok)*EE + lc);
        *(float4*)&vs[ltok][lc] = *(const float4*)(v + base + (long)(t0+ltok)*EE + lc);
        __syncthreads();
        #pragma unroll
        for (int t = 0; t < 16; t++) {
            float a[4], bb[4];
            #pragma unroll
            for (int i = 0; i < 4; i++) a[i] = ks[t][d0+i];
            #pragma unroll
            for (int j = 0; j < 4; j++) bb[j] = vs[t][e0+j];
            #pragma unroll
            for (int i = 0; i < 4; i++)
                #pragma unroll
                for (int j = 0; j < 4; j++) acc[i][j] += a[i]*bb[j];
            if (e0 == 0) {
                #pragma unroll
                for (int i = 0; i < 4; i++) accks[i] += a[i];
            }
        }
        __syncthreads();
    }
    long kvbase = (long)bh * DD * DD;
    #pragma unroll
    for (int i = 0; i < 4; i++)
        #pragma unroll
        for (int j = 0; j < 4; j++)
            atomicAdd(&kv[kvbase + (d0+i)*DD + e0+j], acc[i][j]);
    if (e0 == 0)
        #pragma unroll
        for (int i = 0; i < 4; i++) atomicAdd(&ksum[bh*DD + d0+i], accks[i]);
}

__global__ __launch_bounds__(256) void attn_apply_kernel(const float* __restrict__ q,
                                                         const float* __restrict__ kv,
                                                         const float* __restrict__ ksum,
                                                         float* __restrict__ attn) {
    int bh = blockIdx.x, sblk = blockIdx.y;
    int b = bh >> 4, h = bh & 15;
    int tid = threadIdx.x;
    __shared__ float qs[64][68];
    __shared__ float kvs[64][64];
    __shared__ float kss[64];
    long kvbase = (long)bh * DD * DD;
    #pragma unroll
    for (int r = 0; r < 4; r++) {
        int idx = (r*256 + tid) * 4;
        *(float4*)&kvs[idx >> 6][idx & 63] = *(const float4*)(kv + kvbase + idx);
    }
    if (tid < 64) kss[tid] = ksum[bh*DD + tid];
    long qbase = ((long)b * SS + (long)sblk * 64) * EE + h * DD;
    int ltok = tid >> 4, lc = (tid & 15) * 4;
    #pragma unroll
    for (int r = 0; r < 4; r++)
        *(float4*)&qs[ltok + r*16][lc] =
            *(const float4*)(q + qbase + (long)(ltok + r*16)*EE + lc);
    __syncthreads();
    int tok = tid >> 2, e0 = (tid & 3) * 16;
    float num[16] = {};
    float den = 0.f;
    #pragma unroll 8
    for (int d = 0; d < 64; d++) {
        float qd = qs[tok][d];
        den += qd * kss[d];
        #pragma unroll
        for (int j = 0; j < 16; j++) num[j] += qd * kvs[d][e0+j];
    }
    float r = 1.f / (den + 1e-8f);
    long obase = ((long)b * SS + (long)sblk * 64 + tok) * EE + h * DD + e0;
    #pragma unroll
    for (int j = 0; j < 16; j += 4) {
        float4 o = make_float4(num[j]*r, num[j+1]*r, num[j+2]*r, num[j+3]*r);
        *(float4*)(attn + obase + j) = o;
    }
}

// ---------------- residual / transpose kernels ----------------
__global__ void make_working(const float* __restrict__ qimg,
                             const float* __restrict__ attn_out,
                             const float* __restrict__ ascal,
                             float* __restrict__ work) {
    __shared__ float t[32][33];
    int sx = blockIdx.x * 32, cy = blockIdx.y * 32, b = blockIdx.z;
    int x = threadIdx.x;
    for (int r = threadIdx.y; r < 32; r += 8)
        t[r][x] = qimg[((long)b*EE + cy + r)*SS + sx + x];
    __syncthreads();
    for (int r = threadIdx.y; r < 32; r += 8) {
        long o = ((long)b*SS + sx + r)*EE + cy + x;
        work[o] = t[x][r] + attn_out[o] * ascal[cy + x];
    }
}

__global__ void final_kernel(const float* __restrict__ qimg,
                             const float* __restrict__ work,
                             const float* __restrict__ ffn,
                             const float* __restrict__ fscal,
                             const float* __restrict__ finscal,
                             float* __restrict__ out) {
    __shared__ float t[32][33];
    int sx = blockIdx.x * 32, cy = blockIdx.y * 32, b = blockIdx.z;
    int x = threadIdx.x;
    for (int r = threadIdx.y; r < 32; r += 8) {
        long o = ((long)b*SS + sx + r)*EE + cy + x;
        t[r][x] = (work[o] + ffn[o] * fscal[cy + x]) * finscal[cy + x];
    }
    __syncthreads();
    for (int r = threadIdx.y; r < 32; r += 8) {
        long o = ((long)b*EE + cy + r)*SS + sx + x;
        out[o] = qimg[o] + t[x][r];
    }
}

// ---------------- host launcher ----------------
extern "C" void kernel_launch(void* const* d_in, const int* in_sizes, int n_in,
                              void* d_out, int out_size) {
    const float* qimg   = (const float*)d_in[0];
    const float* kimg   = (const float*)d_in[1];
    const float* vimg   = (const float*)d_in[2];
    const float* grn1_g = (const float*)d_in[3];
    const float* grn1_b = (const float*)d_in[4];
    const float* q_w    = (const float*)d_in[5];
    const float* q_b    = (const float*)d_in[6];
    const float* k_w    = (const float*)d_in[7];
    const float* k_b    = (const float*)d_in[8];
    const float* v_w    = (const float*)d_in[9];
    const float* v_b    = (const float*)d_in[10];
    const float* o_w    = (const float*)d_in[11];
    const float* o_b    = (const float*)d_in[12];
    const float* lnq_w  = (const float*)d_in[13];
    const float* lnq_b  = (const float*)d_in[14];
    const float* lnk_w  = (const float*)d_in[15];
    const float* lnk_b  = (const float*)d_in[16];
    const float* ascal  = (const float*)d_in[17];
    const float* grn2_g = (const float*)d_in[18];
    const float* grn2_b = (const float*)d_in[19];
    const float* w1     = (const float*)d_in[20];
    const float* b1     = (const float*)d_in[21];
    const float* w2     = (const float*)d_in[22];
    const float* b2     = (const float*)d_in[23];
    const float* fscal  = (const float*)d_in[24];
    const float* finscal= (const float*)d_in[25];

    float *adad, *qb, *kb, *vb, *attn, *work, *fn, *kv, *ksum, *sumsq, *meang;
    bf16 *xh, *xl, *wh, *wl, *hh, *hl;
    cudaGetSymbolAddress((void**)&adad, g_adad);
    cudaGetSymbolAddress((void**)&qb,   g_q);
    cudaGetSymbolAddress((void**)&kb,   g_k);
    cudaGetSymbolAddress((void**)&vb,   g_v);
    cudaGetSymbolAddress((void**)&attn, g_attn);
    cudaGetSymbolAddress((void**)&work, g_work);
    cudaGetSymbolAddress((void**)&fn,   g_fn);
    cudaGetSymbolAddress((void**)&xh,   g_xh);
    cudaGetSymbolAddress((void**)&xl,   g_xl);
    cudaGetSymbolAddress((void**)&wh,   g_wh);
    cudaGetSymbolAddress((void**)&wl,   g_wl);
    cudaGetSymbolAddress((void**)&hh,   g_hh);
    cudaGetSymbolAddress((void**)&hl,   g_hl);
    cudaGetSymbolAddress((void**)&kv,   g_kv);
    cudaGetSymbolAddress((void**)&ksum, g_ksum);
    cudaGetSymbolAddress((void**)&sumsq,g_sumsq);
    cudaGetSymbolAddress((void**)&meang,g_meangx);

    cudaFuncSetAttribute(gemm_hmma<0>, cudaFuncAttributeMaxDynamicSharedMemorySize, GSMEM);
    cudaFuncSetAttribute(gemm_hmma<1>, cudaFuncAttributeMaxDynamicSharedMemorySize, GSMEM);

    const long ES = (long)EE * SS;
    dim3 tgrid(SS/32, EE/32, BB);
    dim3 tblk(32, 8);

    // GRN1 on query image
    grn_sumsq_cm<<<BB*EE, 256>>>(qimg, sumsq);
    grn_mean<<<BB, 256>>>(sumsq, meang);
    grn1_apply<<<(int)(BB*ES/1024), 256>>>(qimg, sumsq, meang, grn1_g, grn1_b, adad);

    // Q projection
    cvt_T<<<tgrid, tblk>>>(adad, xh, xl);
    cvt_split<<<EE*EE/1024, 256>>>(q_w, wh, wl);
    gemm_hmma<0><<<dim3(EE/128, BNS/128), 256, GSMEM>>>(xh, xl, wh, wl, q_b,
        qb, nullptr, nullptr, BNS, EE, EE);
    // K projection
    cvt_T<<<tgrid, tblk>>>(kimg, xh, xl);
    cvt_split<<<EE*EE/1024, 256>>>(k_w, wh, wl);
    gemm_hmma<0><<<dim3(EE/128, BNS/128), 256, GSMEM>>>(xh, xl, wh, wl, k_b,
        kb, nullptr, nullptr, BNS, EE, EE);
    // V projection
    cvt_T<<<tgrid, tblk>>>(vimg, xh, xl);
    cvt_split<<<EE*EE/1024, 256>>>(v_w, wh, wl);
    gemm_hmma<0><<<dim3(EE/128, BNS/128), 256, GSMEM>>>(xh, xl, wh, wl, v_b,
        vb, nullptr, nullptr, BNS, EE, EE);

    // LayerNorm + elu+1 (in place)
    ln_elu<<<BNS, 256>>>(qb, lnq_w, lnq_b);
    ln_elu<<<BNS, 256>>>(kb, lnk_w, lnk_b);

    // linear attention
    zero_f<<<(BB*HH*DD*DD + 255)/256, 256>>>(kv, BB*HH*DD*DD);
    zero_f<<<(BB*HH*DD + 255)/256, 256>>>(ksum, BB*HH*DD);
    kvsum_kernel<<<dim3(BB*HH, 16), 256>>>(kb, vb, kv, ksum);
    attn_apply_kernel<<<dim3(BB*HH, SS/64), 256>>>(qb, kv, ksum, attn);

    // O projection -> adad (reused, token-major)
    cvt_split<<<(int)(BNS*(long)EE/1024), 256>>>(attn, xh, xl);
    cvt_split<<<EE*EE/1024, 256>>>(o_w, wh, wl);
    gemm_hmma<0><<<dim3(EE/128, BNS/128), 256, GSMEM>>>(xh, xl, wh, wl, o_b,
        adad, nullptr, nullptr, BNS, EE, EE);

    // working = qimg^T + oproj * attn_scalar (token-major)
    make_working<<<tgrid, tblk>>>(qimg, adad, ascal, work);

    // GRN2 on working (token-major)
    zero_f<<<(BB*EE + 255)/256, 256>>>(sumsq, BB*EE);
    grn2_sumsq<<<dim3(EE/256, SS/256, BB), 256>>>(work, sumsq);
    grn_mean<<<BB, 256>>>(sumsq, meang);
    grn2_apply<<<(int)(BB*ES/1024), 256>>>(work, sumsq, meang, grn2_g, grn2_b, fn);

    // FFN1: fn @ w1^T + b1 -> silu -> bf16 hi/lo hidden
    cvt_split<<<(int)(BNS*(long)EE/1024), 256>>>(fn, xh, xl);
    cvt_split<<<E4*EE/1024, 256>>>(w1, wh, wl);
    gemm_hmma<1><<<dim3(E4/128, BNS/128), 256, GSMEM>>>(xh, xl, wh, wl, b1,
        nullptr, hh, hl, BNS, E4, EE);

    // FFN2: h @ w2^T + b2 -> ffn (reuse attn buffer)
    cvt_split<<<EE*E4/1024, 256>>>(w2, wh, wl);
    gemm_hmma<0><<<dim3(EE/128, BNS/128), 256, GSMEM>>>(hh, hl, wh, wl, b2,
        attn, nullptr, nullptr, BNS, EE, E4);

    // final residual (transpose back to channel-major)
    final_kernel<<<tgrid, tblk>>>(qimg, work, attn, fscal, finscal, (float*)d_out);
}